// round 2
// baseline (speedup 1.0000x reference)
#include <cuda_runtime.h>
#include <cuda_bf16.h>

// PhysicsRouter fused single-kernel version.
// logits = X @ W^T + mass*bias; softmax; top-2; aux loss.
// X [16384, 4096] f32, mass [16384], W [4, 4096], bias [4].
// Output (f32): [0,65536) logits | [65536,98304) top_k_idx | [98304] aux | [98305,131073) top_k_w

#define C_DIM 4096
#define E_DIM 4
#define N_TOK 16384
#define GROUP 8                   // tokens per warp
#define WARPS_PER_BLOCK 4
#define BLOCK_THREADS (WARPS_PER_BLOCK * 32)
#define GRID_BLOCKS (N_TOK / (GROUP * WARPS_PER_BLOCK))   // 512

__device__ float g_partial[GRID_BLOCKS][E_DIM];
__device__ unsigned int g_count = 0;   // wraps back to 0 every full grid -> graph-replay safe

__global__ __launch_bounds__(BLOCK_THREADS)
void router_fused(const float* __restrict__ X,
                  const float* __restrict__ mass,
                  const float* __restrict__ W,
                  const float* __restrict__ bias,
                  float* __restrict__ out)
{
    const int tid   = threadIdx.x;
    const int warp  = tid >> 5;
    const int lane  = tid & 31;
    const int gwarp = blockIdx.x * WARPS_PER_BLOCK + warp;
    const long token0 = (long)gwarp * GROUP;

    float acc[GROUP][E_DIM];
#pragma unroll
    for (int t = 0; t < GROUP; t++)
#pragma unroll
        for (int e = 0; e < E_DIM; e++) acc[t][e] = 0.0f;

    // 16 iterations x 256 columns. Gate float4s loaded once per iter, reused x8 tokens.
#pragma unroll 1
    for (int it = 0; it < C_DIM / 256; ++it) {
        const int colA = it * 256 + lane * 4;
        const int colB = colA + 128;
        float4 gA[E_DIM], gB[E_DIM];
#pragma unroll
        for (int e = 0; e < E_DIM; e++) {
            gA[e] = __ldg((const float4*)(W + e * C_DIM + colA));
            gB[e] = __ldg((const float4*)(W + e * C_DIM + colB));
        }
#pragma unroll
        for (int t = 0; t < GROUP; t++) {
            const float* xrow = X + (token0 + t) * C_DIM;
            const float4 xa = __ldg((const float4*)(xrow + colA));
            const float4 xb = __ldg((const float4*)(xrow + colB));
#pragma unroll
            for (int e = 0; e < E_DIM; e++) {
                float a = acc[t][e];
                a = fmaf(xa.x, gA[e].x, a);
                a = fmaf(xa.y, gA[e].y, a);
                a = fmaf(xa.z, gA[e].z, a);
                a = fmaf(xa.w, gA[e].w, a);
                a = fmaf(xb.x, gB[e].x, a);
                a = fmaf(xb.y, gB[e].y, a);
                a = fmaf(xb.z, gB[e].z, a);
                a = fmaf(xb.w, gB[e].w, a);
                acc[t][e] = a;
            }
        }
    }

    // Butterfly-reduce all 32 accumulators across the warp.
#pragma unroll
    for (int t = 0; t < GROUP; t++)
#pragma unroll
        for (int e = 0; e < E_DIM; e++)
#pragma unroll
            for (int s = 16; s > 0; s >>= 1)
                acc[t][e] += __shfl_xor_sync(0xFFFFFFFFu, acc[t][e], s);

    // Lane t (t < GROUP) takes token0 + t. Static-index selection.
    float l[E_DIM] = {0.f, 0.f, 0.f, 0.f};
#pragma unroll
    for (int t = 0; t < GROUP; t++) {
        if (lane == t) {
#pragma unroll
            for (int e = 0; e < E_DIM; e++) l[e] = acc[t][e];
        }
    }

    float p[E_DIM] = {0.f, 0.f, 0.f, 0.f};

    if (lane < GROUP) {
        const long token = token0 + lane;
        const float m = __ldg(mass + token);
        const float4 b = __ldg((const float4*)bias);
        l[0] = fmaf(m, b.x, l[0]);
        l[1] = fmaf(m, b.y, l[1]);
        l[2] = fmaf(m, b.z, l[2]);
        l[3] = fmaf(m, b.w, l[3]);

        float4 lo; lo.x = l[0]; lo.y = l[1]; lo.z = l[2]; lo.w = l[3];
        *(float4*)(out + token * E_DIM) = lo;

        const float mx = fmaxf(fmaxf(l[0], l[1]), fmaxf(l[2], l[3]));
        p[0] = expf(l[0] - mx);
        p[1] = expf(l[1] - mx);
        p[2] = expf(l[2] - mx);
        p[3] = expf(l[3] - mx);
        const float inv = 1.0f / (p[0] + p[1] + p[2] + p[3]);
        p[0] *= inv; p[1] *= inv; p[2] *= inv; p[3] *= inv;

        // top-2, lowest-index tie break (strict > keeps earlier index)
        int i1 = 0; float v1 = p[0];
#pragma unroll
        for (int e = 1; e < E_DIM; e++)
            if (p[e] > v1) { v1 = p[e]; i1 = e; }
        int i2 = -1; float v2 = -1.0f;
#pragma unroll
        for (int e = 0; e < E_DIM; e++)
            if (e != i1 && p[e] > v2) { v2 = p[e]; i2 = e; }

        float* out_idx = out + (long)N_TOK * E_DIM;
        float* out_w   = out + (long)N_TOK * E_DIM + (long)N_TOK * 2 + 1;
        out_idx[token * 2 + 0] = (float)i1;
        out_idx[token * 2 + 1] = (float)i2;
        out_w[token * 2 + 0]   = v1;
        out_w[token * 2 + 1]   = v2;
    }

    // ---- expert importance: warp reduce -> block reduce -> per-block partial ----
#pragma unroll
    for (int e = 0; e < E_DIM; e++)
#pragma unroll
        for (int s = 16; s > 0; s >>= 1)
            p[e] += __shfl_xor_sync(0xFFFFFFFFu, p[e], s);

    __shared__ float s_imp[WARPS_PER_BLOCK][E_DIM];
    if (lane == 0) {
#pragma unroll
        for (int e = 0; e < E_DIM; e++) s_imp[warp][e] = p[e];
    }
    __syncthreads();

    __shared__ bool s_is_last;
    if (tid == 0) {
#pragma unroll
        for (int e = 0; e < E_DIM; e++)
            g_partial[blockIdx.x][e] = s_imp[0][e] + s_imp[1][e] + s_imp[2][e] + s_imp[3][e];
        __threadfence();
        const unsigned int v = atomicInc(&g_count, GRID_BLOCKS - 1);
        s_is_last = (v == GRID_BLOCKS - 1);
    }
    __syncthreads();

    // ---- last block finalizes aux loss ----
    if (s_is_last) {
        __shared__ double s_sum[BLOCK_THREADS];
        const int e = tid & 3;
        const int chunk = tid >> 2;                  // 0..31
        const int per = GRID_BLOCKS / 32;            // 16
        double s = 0.0;
        for (int j = chunk * per; j < (chunk + 1) * per; j++)
            s += (double)g_partial[j][e];
        s_sum[tid] = s;
        __syncthreads();
        if (tid < E_DIM) {
            double imp = 0.0;
#pragma unroll
            for (int k = 0; k < 32; k++)
                imp += s_sum[e + 4 * k];            // e == tid here
            s_sum[tid] = imp;                        // reuse slot for final imp[e]
        }
        __syncthreads();
        if (tid == 0) {
            const double target = (double)N_TOK / (double)E_DIM;
            double loss = 0.0;
#pragma unroll
            for (int k = 0; k < E_DIM; k++) {
                const double d = s_sum[k] - target;
                loss += d * d;
            }
            out[(long)N_TOK * E_DIM + (long)N_TOK * 2] = (float)(loss / E_DIM);
        }
    }
}

extern "C" void kernel_launch(void* const* d_in, const int* in_sizes, int n_in,
                              void* d_out, int out_size)
{
    const float* X    = (const float*)d_in[0];
    const float* mass = (const float*)d_in[1];
    const float* W    = (const float*)d_in[2];
    const float* bias = (const float*)d_in[3];
    float* out = (float*)d_out;

    router_fused<<<GRID_BLOCKS, BLOCK_THREADS>>>(X, mass, W, bias, out);
}